// round 16
// baseline (speedup 1.0000x reference)
#include <cuda_runtime.h>
#include <math.h>

#define NPTS   8192
#define NPTOT  16384
#define KNBR   16
#define NTRI   (2*3*4096*64)
#define NCNT   (2*3*4096)
#define OUT_C   49152
#define OUT_TRI (49152 + 1048576)
#define GRES   16
#define GCELLS 4096
#define KCAP   96
#define KNNG_BLOCKS 4096
#define XUP_BLOCKS  1024

__device__ float4 g_pts[NPTOT];          // x,y,z,|p|^2
__device__ int    g_idx[NPTOT*KNBR];
__device__ int    g_ij[NPTOT];
__device__ float  g_c[NPTOT*64];
__device__ float  g_xA[NPTOT*32];
__device__ float  g_xB[NPTOT*32];
__device__ float  g_cnt[NCNT];
__device__ float  g_wt[5*16384];
__device__ int    g_ccnt[2*GCELLS];
__device__ int    g_cfill[2*GCELLS];
__device__ int    g_cstart[2*GCELLS + 1];
__device__ float4 g_sorted[NPTOT];
__device__ int    g_sidx[NPTOT];

__device__ __forceinline__ float d2f(float qx,float qy,float qz,float qs, float4 c){
    float dot = fmaf(qx,c.x, fmaf(qy,c.y, qz*c.z));
    return fmaf(-2.0f, dot, qs + c.w);
}
__device__ __forceinline__ int cellcoord(float v){
    int c = (int)((v + 0.5f) * 16.0f);
    return min(max(c, 0), 15);
}

// ---------------- fused prep: zero + stem + wt transpose + xyz copy ----------------
__global__ void k_prep(const float* __restrict__ xyz, const float* __restrict__ ws,
                       const float* __restrict__ bs, const float* __restrict__ wcv,
                       float* __restrict__ out) {
    int gid = blockIdx.x*blockDim.x + threadIdx.x;   // grid covers NTRI exactly
    out[OUT_TRI + gid] = 0.f;                        // zero triplane
    if (gid < NCNT) g_cnt[gid] = 0.f;
    if (gid < 2*GCELLS) { g_ccnt[gid] = 0; g_cfill[gid] = 0; }
    if (gid < 5*16384) {                             // wcv transpose
        int blk = gid / 16384, r = gid % 16384;
        int o = r >> 9, c = (r >> 4) & 31, s = r & 15;
        g_wt[blk*16384 + (c*16+s)*32 + o] = wcv[gid];
    }
    if (gid < NPTOT*3) out[gid] = xyz[gid];          // output 0
    if (gid < NPTOT*64) {                            // stem
        int p = gid >> 6, d = gid & 63;
        float x = xyz[p*3+0], y = xyz[p*3+1], z = xyz[p*3+2];
        g_c[gid] = fmaf(z, ws[128+d], fmaf(y, ws[64+d], fmaf(x, ws[d], bs[d])));
        if (d == 0) {
            g_pts[p] = make_float4(x, y, z, fmaf(z, z, fmaf(y, y, x*x)));
            const float den = 1.101f;
            float px = x/den + 0.5f, py = y/den + 0.5f, pz = z/den + 0.5f;
            int ix = (int)(px*64.0f); ix = min(max(ix,0),63);
            int iy = (int)(py*64.0f); iy = min(max(iy,0),63);
            int iz = (int)(pz*64.0f); iz = min(max(iz,0),63);
            g_ij[p] = ix | (iy<<6) | (iz<<12);
        }
    }
}

// cell counting must run after g_ccnt is zeroed (separate launch)
__global__ void k_cellcnt() {
    int p = blockIdx.x*blockDim.x + threadIdx.x;
    if (p >= NPTOT) return;
    float4 q = g_pts[p];
    int cell = (p>>13)*GCELLS +
               (cellcoord(q.z)*16 + cellcoord(q.y))*16 + cellcoord(q.x);
    atomicAdd(&g_ccnt[cell], 1);
}

// ---------------- grid build ----------------
__global__ void k_scan() {
    __shared__ int part[256], off[256];
    int t = threadIdx.x;
    int base = t*32;
    int loc[32];
    int run = 0;
    #pragma unroll
    for (int j = 0; j < 32; j++) { loc[j] = run; run += g_ccnt[base+j]; }
    part[t] = run;
    __syncthreads();
    if (t < 32) {
        int tmp[8]; int s = 0;
        #pragma unroll
        for (int j = 0; j < 8; j++) { tmp[j] = s; s += part[t*8+j]; }
        int run2 = s;
        #pragma unroll
        for (int o2 = 1; o2 < 32; o2 <<= 1) {
            int v = __shfl_up_sync(0xffffffffu, run2, o2);
            if (t >= o2) run2 += v;
        }
        int excl = run2 - s;
        #pragma unroll
        for (int j = 0; j < 8; j++) off[t*8+j] = excl + tmp[j];
        if (t == 31) g_cstart[2*GCELLS] = excl + s;
    }
    __syncthreads();
    int o = off[t];
    #pragma unroll
    for (int j = 0; j < 32; j++) g_cstart[base+j] = loc[j] + o;
}

__global__ void k_gscat() {
    int p = blockIdx.x*blockDim.x + threadIdx.x;
    if (p >= NPTOT) return;
    float4 q = g_pts[p];
    int cell = (p>>13)*GCELLS +
               (cellcoord(q.z)*16 + cellcoord(q.y))*16 + cellcoord(q.x);
    int pos = g_cstart[cell] + atomicAdd(&g_cfill[cell], 1);
    g_sorted[pos] = q;
    g_sidx[pos] = p;
}

// ---------------- grid KNN + fused xup (independent work, one launch) ----------------
// blocks [0, KNNG_BLOCKS): KNN, warp per query, exact with box-face guard.
// blocks [KNNG_BLOCKS, KNNG_BLOCKS+XUP_BLOCKS): x = relu(c @ w0 + b0) -> g_xA.
__global__ void __launch_bounds__(128) k_knng(const float* __restrict__ w0,
                                              const float* __restrict__ b0) {
    __shared__ float bufd[4][KCAP];
    __shared__ int   bufi[4][KCAP];
    __shared__ int   bcnt[4];

    if (blockIdx.x >= KNNG_BLOCKS) {
        // ---- xup part: 512 outputs per block, coalesced ----
        int base = (blockIdx.x - KNNG_BLOCKS) * 512;
        #pragma unroll
        for (int e = 0; e < 4; e++) {
            int gid = base + e*128 + threadIdx.x;
            int n = gid >> 5, h = gid & 31;
            const float* cr = g_c + n*64;
            float a0 = b0[h], a1 = 0.f;
            #pragma unroll
            for (int d = 0; d < 64; d += 2) {
                a0 = fmaf(cr[d],   w0[d*32+h],     a0);
                a1 = fmaf(cr[d+1], w0[(d+1)*32+h], a1);
            }
            g_xA[gid] = fmaxf(a0 + a1, 0.f);
        }
        return;
    }

    int w = threadIdx.x >> 5, lane = threadIdx.x & 31;
    int p = blockIdx.x*4 + w;
    float4 Q = g_pts[p];
    int cbase = (p>>13)*GCELLS;
    int sbase = (p>>13)*NPTS;
    int cx = cellcoord(Q.x), cy = cellcoord(Q.y), cz = cellcoord(Q.z);
    const float h = 0.0625f;

    int r = 2;
    bool fb = false;
    for (;;) {
        int xlo = max(cx-r,0), xhi = min(cx+r,15);
        int ylo = max(cy-r,0), yhi = min(cy+r,15);
        int zlo = max(cz-r,0), zhi = min(cz+r,15);

        float lmin = 1e30f;
        int ord = 0;
        for (int z = zlo; z <= zhi; z++)
            for (int y = ylo; y <= yhi; y++) {
                int row = cbase + (z*16 + y)*16;
                int s0 = g_cstart[row + xlo];
                int s1 = g_cstart[row + xhi + 1];
                int len = s1 - s0;
                int t0 = (lane - ord) & 31;
                for (int t = t0; t < len; t += 32)
                    lmin = fminf(lmin, d2f(Q.x,Q.y,Q.z,Q.w, g_sorted[s0 + t]));
                ord += len;
            }
        if (ord < KNBR) { r++; continue; }

        float T = 0.f;
        {
            float vv = lmin;
            for (int rr = 0; rr < 16; rr++) {
                float mv = vv; int ml = lane;
                #pragma unroll
                for (int off = 16; off; off >>= 1) {
                    float ov = __shfl_xor_sync(0xffffffffu, mv, off);
                    int   ol = __shfl_xor_sync(0xffffffffu, ml, off);
                    if (ov < mv || (ov == mv && ol < ml)) { mv = ov; ml = ol; }
                }
                T = mv;
                if (lane == ml) vv = 1e30f;
            }
        }
        if (lane == 0) bcnt[w] = 0;
        __syncwarp();

        for (int z = zlo; z <= zhi; z++)
            for (int y = ylo; y <= yhi; y++) {
                int row = cbase + (z*16 + y)*16;
                int s0 = g_cstart[row + xlo];
                int s1 = g_cstart[row + xhi + 1];
                for (int j = s0 + lane; j < s1; j += 32) {
                    float dd = d2f(Q.x,Q.y,Q.z,Q.w, g_sorted[j]);
                    if (dd <= T) {
                        int pos = atomicAdd(&bcnt[w], 1);
                        if (pos < KCAP) { bufd[w][pos] = dd; bufi[w][pos] = g_sidx[j]; }
                    }
                }
            }
        __syncwarp();
        int cnt = bcnt[w];
        if (cnt > KCAP) { fb = true; break; }

        float d16 = 0.f;
        for (int rr = 0; rr < KNBR; rr++) {
            float lbd = 1e30f; int lbi = 0x7fffffff; int lpos = -1;
            for (int j = lane; j < cnt; j += 32) {
                float d = bufd[w][j]; int ii = bufi[w][j];
                if (d < lbd || (d == lbd && ii < lbi)) { lbd = d; lbi = ii; lpos = j; }
            }
            float bd = lbd; int bi = lbi;
            #pragma unroll
            for (int off = 16; off; off >>= 1) {
                float od = __shfl_xor_sync(0xffffffffu, bd, off);
                int   oi = __shfl_xor_sync(0xffffffffu, bi, off);
                if (od < bd || (od == bd && oi < bi)) { bd = od; bi = oi; }
            }
            if (lpos >= 0 && lbi == bi) bufd[w][lpos] = 1e30f;
            if (lane == 0) g_idx[p*KNBR + rr] = bi;
            d16 = bd;
            __syncwarp();
        }

        float g = 1e30f;
        if (xlo > 0)  g = fminf(g, Q.x - (-0.5f + xlo*h));
        if (xhi < 15) g = fminf(g, (-0.5f + (xhi+1)*h) - Q.x);
        if (ylo > 0)  g = fminf(g, Q.y - (-0.5f + ylo*h));
        if (yhi < 15) g = fminf(g, (-0.5f + (yhi+1)*h) - Q.y);
        if (zlo > 0)  g = fminf(g, Q.z - (-0.5f + zlo*h));
        if (zhi < 15) g = fminf(g, (-0.5f + (zhi+1)*h) - Q.z);
        if (d16 < g*g*0.99999f) break;
        r++;
        if (r > 18) break;
    }

    if (fb && lane == 0) {
        const float4* pts = g_pts + sbase;
        float td[KNBR]; int ti[KNBR];
        #pragma unroll
        for (int rr = 0; rr < KNBR; rr++) { td[rr] = 1e30f; ti[rr] = 0x7fffffff; }
        for (int m = 0; m < NPTS; m++) {
            float dd = d2f(Q.x,Q.y,Q.z,Q.w, pts[m]);
            if (dd < td[KNBR-1] || (dd == td[KNBR-1] && m < ti[KNBR-1])) {
                float cd = dd; int ci = m;
                #pragma unroll
                for (int rr = 0; rr < KNBR; rr++) {
                    bool lt = (cd < td[rr]) || (cd == td[rr] && ci < ti[rr]);
                    if (lt) { float t1=td[rr]; int t2=ti[rr]; td[rr]=cd; ti[rr]=ci; cd=t1; ci=t2; }
                }
            }
        }
        for (int rr = 0; rr < KNBR; rr++) g_idx[p*KNBR + rr] = sbase + ti[rr];
    }
}

// ---------------- fused FKAConv + w2 + residual + next-block x; CTA = 8 points ----------------
// (exact round-13 form: butterfly maxpool + b-side dedup, coalesced epilogues)
__global__ void __launch_bounds__(128) k_fka(int blk, int last, int bufsel,
    const float* __restrict__ fc1, const float* __restrict__ fc2,
    const float* __restrict__ fc3, const float* __restrict__ alpha,
    const float* __restrict__ beta, const float* __restrict__ w2,
    const float* __restrict__ b2, const float* __restrict__ w0n,
    const float* __restrict__ b0n, float* __restrict__ outc)
{
    __shared__ float sfc1[48], sfc2[512], sfc3[512];
    __shared__ float sM[2048];   // [warp][pt][k][s]; reused as sC[warp][pt][64]
    __shared__ float sF[4096];   // [ptCTA 0..7][cs 0..511]
    __shared__ float sP[1024];   // [warp][ptCTA][o] wcv partials
    __shared__ float sR[256];    // [ptCTA][o]
    __shared__ int   sI[128];    // [ptCTA][k]

    const float* __restrict__ xin  = bufsel ? g_xB : g_xA;
    float* __restrict__       xout = bufsel ? g_xA : g_xB;

    int tid = threadIdx.x, w = tid >> 5, lane = tid & 31;
    for (int i = tid; i < 48;  i += 128) sfc1[i] = fc1[i];
    for (int i = tid; i < 512; i += 128) { sfc2[i] = fc2[i]; sfc3[i] = fc3[i]; }
    __syncthreads();

    int half = lane >> 4, k = lane & 15;
    int hbase = lane & 16;
    int p = blockIdx.x*8 + w*2 + half;
    int ik = g_idx[p*KNBR + k];
    sI[(w*2+half)*16 + k] = ik;
    float4 q  = g_pts[p];
    float4 nb = g_pts[ik];
    float dx = nb.x-q.x, dy = nb.y-q.y, dz = nb.z-q.z;
    float dist = sqrtf(dx*dx + dy*dy + dz*dz + 1e-12f);
    float zz = beta[0] - alpha[0]*dist;
    float dwr = 1.0f/(1.0f + expf(-zz));
    float sm = dwr;
    #pragma unroll
    for (int off = 8; off; off >>= 1) sm += __shfl_xor_sync(0xffffffffu, sm, off);
    float dw = dwr / (sm + 1e-6f) * 16.0f;

    float a[16], b[16], c2[16];
    #pragma unroll
    for (int s = 0; s < 16; s++)
        a[s] = fmaxf(fmaf(dx, sfc1[s], fmaf(dy, sfc1[16+s], dz*sfc1[32+s])), 0.f);
    #pragma unroll
    for (int s = 0; s < 16; s++) {
        float v = a[s]*dw;
        #pragma unroll
        for (int off = 8; off; off >>= 1) v = fmaxf(v, __shfl_xor_sync(0xffffffffu, v, off));
        b[s] = v;
    }
    // fc2: a-part per lane; b-part identical across the half -> own-column + shuffle
    {
        float bp = 0.f;
        #pragma unroll
        for (int r = 0; r < 16; r++) bp = fmaf(b[r], sfc2[(16+r)*16 + k], bp);
        #pragma unroll
        for (int s = 0; s < 16; s++) c2[s] = 0.f;
        #pragma unroll 4
        for (int r = 0; r < 16; r++) {
            float va = a[r];
            #pragma unroll
            for (int s = 0; s < 16; s++)
                c2[s] = fmaf(va, sfc2[r*16+s], c2[s]);
        }
        #pragma unroll
        for (int s = 0; s < 16; s++)
            c2[s] += __shfl_sync(0xffffffffu, bp, hbase + s);
    }
    #pragma unroll
    for (int s = 0; s < 16; s++) a[s] = fmaxf(c2[s], 0.f);
    #pragma unroll
    for (int s = 0; s < 16; s++) {
        float v = a[s]*dw;
        #pragma unroll
        for (int off = 8; off; off >>= 1) v = fmaxf(v, __shfl_xor_sync(0xffffffffu, v, off));
        b[s] = v;
    }
    // fc3: same dedup
    {
        float bp = 0.f;
        #pragma unroll
        for (int r = 0; r < 16; r++) bp = fmaf(b[r], sfc3[(16+r)*16 + k], bp);
        #pragma unroll
        for (int s = 0; s < 16; s++) c2[s] = 0.f;
        #pragma unroll 4
        for (int r = 0; r < 16; r++) {
            float va = a[r];
            #pragma unroll
            for (int s = 0; s < 16; s++)
                c2[s] = fmaf(va, sfc3[r*16+s], c2[s]);
        }
        #pragma unroll
        for (int s = 0; s < 16; s++)
            c2[s] += __shfl_sync(0xffffffffu, bp, hbase + s);
    }
    {   // m = relu(m3)*dw -> smem
        float4* md = (float4*)&sM[((w*2+half)*16 + k)*16];
        md[0] = make_float4(fmaxf(c2[0],0.f)*dw, fmaxf(c2[1],0.f)*dw,
                            fmaxf(c2[2],0.f)*dw, fmaxf(c2[3],0.f)*dw);
        md[1] = make_float4(fmaxf(c2[4],0.f)*dw, fmaxf(c2[5],0.f)*dw,
                            fmaxf(c2[6],0.f)*dw, fmaxf(c2[7],0.f)*dw);
        md[2] = make_float4(fmaxf(c2[8],0.f)*dw, fmaxf(c2[9],0.f)*dw,
                            fmaxf(c2[10],0.f)*dw, fmaxf(c2[11],0.f)*dw);
        md[3] = make_float4(fmaxf(c2[12],0.f)*dw, fmaxf(c2[13],0.f)*dw,
                            fmaxf(c2[14],0.f)*dw, fmaxf(c2[15],0.f)*dw);
    }
    __syncwarp();

    // f[c][s] = sum_k nb_x[k][c]*m[k][s]; lane = c (own warp's 2 points)
    #pragma unroll
    for (int pt = 0; pt < 2; pt++) {
        float f[16];
        #pragma unroll
        for (int s = 0; s < 16; s++) f[s] = 0.f;
        const int* ip = &sI[(w*2+pt)*16];
        #pragma unroll 4
        for (int kk = 0; kk < 16; kk++) {
            float nbx = xin[ip[kk]*32 + lane];
            const float4* mv = (const float4*)&sM[((w*2+pt)*16 + kk)*16];
            float4 v0 = mv[0], v1 = mv[1], v2 = mv[2], v3 = mv[3];
            f[0]=fmaf(nbx,v0.x,f[0]);  f[1]=fmaf(nbx,v0.y,f[1]);
            f[2]=fmaf(nbx,v0.z,f[2]);  f[3]=fmaf(nbx,v0.w,f[3]);
            f[4]=fmaf(nbx,v1.x,f[4]);  f[5]=fmaf(nbx,v1.y,f[5]);
            f[6]=fmaf(nbx,v1.z,f[6]);  f[7]=fmaf(nbx,v1.w,f[7]);
            f[8]=fmaf(nbx,v2.x,f[8]);  f[9]=fmaf(nbx,v2.y,f[9]);
            f[10]=fmaf(nbx,v2.z,f[10]); f[11]=fmaf(nbx,v2.w,f[11]);
            f[12]=fmaf(nbx,v3.x,f[12]); f[13]=fmaf(nbx,v3.y,f[13]);
            f[14]=fmaf(nbx,v3.z,f[14]); f[15]=fmaf(nbx,v3.w,f[15]);
        }
        float4* fd = (float4*)&sF[(w*2+pt)*512 + lane*16];
        fd[0] = make_float4(f[0],f[1],f[2],f[3]);
        fd[1] = make_float4(f[4],f[5],f[6],f[7]);
        fd[2] = make_float4(f[8],f[9],f[10],f[11]);
        fd[3] = make_float4(f[12],f[13],f[14],f[15]);
    }
    __syncthreads();

    // wcv: warp w covers cs in [w*128,(w+1)*128), accumulates ALL 8 CTA points.
    {
        int csoff = lane >> 3, o0 = (lane & 7) << 2;
        const float* wtb = g_wt + blk*16384;
        float acc[8][4];
        #pragma unroll
        for (int pt = 0; pt < 8; pt++)
            #pragma unroll
            for (int j = 0; j < 4; j++) acc[pt][j] = 0.f;
        int wbase = w*128;
        #pragma unroll 4
        for (int g2 = 0; g2 < 32; g2++) {
            int cs = wbase + (g2<<2) + csoff;
            float4 wv = *(const float4*)(wtb + (cs<<5) + o0);
            #pragma unroll
            for (int pt = 0; pt < 8; pt++) {
                float fv = sF[pt*512 + cs];
                acc[pt][0]=fmaf(fv,wv.x,acc[pt][0]);
                acc[pt][1]=fmaf(fv,wv.y,acc[pt][1]);
                acc[pt][2]=fmaf(fv,wv.z,acc[pt][2]);
                acc[pt][3]=fmaf(fv,wv.w,acc[pt][3]);
            }
        }
        #pragma unroll
        for (int off = 8; off <= 16; off <<= 1) {
            #pragma unroll
            for (int pt = 0; pt < 8; pt++) {
                acc[pt][0] += __shfl_xor_sync(0xffffffffu, acc[pt][0], off);
                acc[pt][1] += __shfl_xor_sync(0xffffffffu, acc[pt][1], off);
                acc[pt][2] += __shfl_xor_sync(0xffffffffu, acc[pt][2], off);
                acc[pt][3] += __shfl_xor_sync(0xffffffffu, acc[pt][3], off);
            }
        }
        if (csoff == 0) {
            #pragma unroll
            for (int pt = 0; pt < 8; pt++)
                *(float4*)&sP[(w*8 + pt)*32 + o0] =
                    make_float4(acc[pt][0], acc[pt][1], acc[pt][2], acc[pt][3]);
        }
    }
    __syncthreads();

    // cross-warp reduce + relu -> sR[pt*32+o]
    {
        #pragma unroll
        for (int ii = 0; ii < 2; ii++) {
            int idx = tid*2 + ii;
            float s = sP[idx] + sP[256+idx] + sP[512+idx] + sP[768+idx];
            sR[idx] = fmaxf(s, 0.f);
        }
    }
    __syncwarp();

    // c = relu(r @ w2 + b2 + c); coalesced scalar w2 loads
    float* sC = &sM[w*512];
    int d0 = lane, d1 = lane + 32;
    #pragma unroll
    for (int pt = 0; pt < 2; pt++) {
        int p2 = blockIdx.x*8 + w*2 + pt;
        float acc0 = b2[d0], acc1 = b2[d1];
        const float* rr = &sR[(w*2+pt)*32];
        #pragma unroll 8
        for (int h = 0; h < 32; h++) {
            float rh = rr[h];
            acc0 = fmaf(rh, w2[h*64 + d0], acc0);
            acc1 = fmaf(rh, w2[h*64 + d1], acc1);
        }
        float c0 = g_c[p2*64 + d0], c1 = g_c[p2*64 + d1];
        float v0 = fmaxf(acc0 + c0, 0.f), v1 = fmaxf(acc1 + c1, 0.f);
        g_c[p2*64 + d0] = v0;
        g_c[p2*64 + d1] = v1;
        sC[pt*64 + d0] = v0;
        sC[pt*64 + d1] = v1;
        if (last) { outc[p2*64 + d0] = v0; outc[p2*64 + d1] = v1; }
    }
    __syncwarp();

    // next block's x = relu(c_new @ w0n + b0n) into the OTHER buffer (no race)
    if (!last) {
        #pragma unroll
        for (int pt = 0; pt < 2; pt++) {
            int p2 = blockIdx.x*8 + w*2 + pt;
            const float* cc = &sC[pt*64];
            float acc = b0n[lane];
            #pragma unroll 16
            for (int d = 0; d < 64; d++)
                acc = fmaf(cc[d], w0n[d*32 + lane], acc);
            xout[p2*32 + lane] = fmaxf(acc, 0.f);
        }
    }
}

// ---------------- triplane ----------------
__global__ void k_scatter(float* __restrict__ tri) {
    int gid = blockIdx.x*blockDim.x + threadIdx.x;
    if (gid >= NPTOT*64) return;
    int p = gid >> 6, d = gid & 63;
    int code = g_ij[p];
    int i0 = code & 63, i1 = (code>>6)&63, i2 = (code>>12)&63;
    int base = (p >> 13) * 3 * 4096;
    int c01 = base + (i0*64+i1);
    int c02 = base + 4096 + (i0*64+i2);
    int c12 = base + 8192 + (i1*64+i2);
    float v = g_c[gid];
    atomicAdd(&tri[c01*64 + d], v);
    atomicAdd(&tri[c02*64 + d], v);
    atomicAdd(&tri[c12*64 + d], v);
    if (d == 0) {
        atomicAdd(&g_cnt[c01], 1.f);
        atomicAdd(&g_cnt[c02], 1.f);
        atomicAdd(&g_cnt[c12], 1.f);
    }
}
__global__ void k_norm(float* __restrict__ tri) {
    int gid = blockIdx.x*blockDim.x + threadIdx.x;
    if (gid >= NTRI) return;
    tri[gid] = tri[gid] / fmaxf(g_cnt[gid >> 6], 1.f);
}

extern "C" void kernel_launch(void* const* d_in, const int* in_sizes, int n_in,
                              void* d_out, int out_size) {
    const float* xyz    = (const float*)d_in[0];
    const float* w_stem = (const float*)d_in[1];
    const float* b_stem = (const float*)d_in[2];
    const float* w0     = (const float*)d_in[3];
    const float* b0     = (const float*)d_in[4];
    const float* fc1    = (const float*)d_in[5];
    const float* fc2    = (const float*)d_in[6];
    const float* fc3    = (const float*)d_in[7];
    const float* wcv    = (const float*)d_in[8];
    const float* alpha  = (const float*)d_in[9];
    const float* beta   = (const float*)d_in[10];
    const float* w2     = (const float*)d_in[11];
    const float* b2     = (const float*)d_in[12];
    float* out = (float*)d_out;

    k_prep<<<6144, 256>>>(xyz, w_stem, b_stem, wcv, out);
    k_cellcnt<<<64, 256>>>();
    k_scan<<<1, 256>>>();
    k_gscat<<<64, 256>>>();
    k_knng<<<KNNG_BLOCKS + XUP_BLOCKS, 128>>>(w0, b0);
    for (int i = 0; i < 5; i++) {
        int last = (i == 4);
        k_fka<<<2048, 128>>>(i, last, i & 1,
                             fc1 + i*48, fc2 + i*512, fc3 + i*512,
                             alpha + i, beta + i, w2 + i*2048, b2 + i*64,
                             w0 + (last ? 0 : (i+1)*2048),
                             b0 + (last ? 0 : (i+1)*32),
                             out + OUT_C);
    }
    k_scatter<<<4096, 256>>>(out + OUT_TRI);
    k_norm<<<6144, 256>>>(out + OUT_TRI);
}

// round 17
// speedup vs baseline: 1.0370x; 1.0370x over previous
#include <cuda_runtime.h>
#include <math.h>

#define NPTS   8192
#define NPTOT  16384
#define KNBR   16
#define NTRI   (2*3*4096*64)
#define NCNT   (2*3*4096)
#define OUT_C   49152
#define OUT_TRI (49152 + 1048576)
#define GRES   16
#define GCELLS 4096
#define KCAP   96

__device__ float4 g_pts[NPTOT];          // x,y,z,|p|^2
__device__ int    g_idx[NPTOT*KNBR];
__device__ int    g_ij[NPTOT];
__device__ float  g_c[NPTOT*64];
__device__ float  g_xA[NPTOT*32];
__device__ float  g_xB[NPTOT*32];
__device__ float  g_cnt[NCNT];
__device__ float  g_wt[5*16384];
__device__ int    g_ccnt[2*GCELLS];
__device__ int    g_cfill[2*GCELLS];
__device__ int    g_cstart[2*GCELLS + 1];
__device__ float4 g_sorted[NPTOT];
__device__ int    g_sidx[NPTOT];

__device__ __forceinline__ float d2f(float qx,float qy,float qz,float qs, float4 c){
    float dot = fmaf(qx,c.x, fmaf(qy,c.y, qz*c.z));
    return fmaf(-2.0f, dot, qs + c.w);
}
__device__ __forceinline__ int cellcoord(float v){
    int c = (int)((v + 0.5f) * 16.0f);
    return min(max(c, 0), 15);
}

// ---------------- fused prep: zero + stem + wt transpose + xyz copy ----------------
__global__ void k_prep(const float* __restrict__ xyz, const float* __restrict__ ws,
                       const float* __restrict__ bs, const float* __restrict__ wcv,
                       float* __restrict__ out) {
    int gid = blockIdx.x*blockDim.x + threadIdx.x;   // grid covers NTRI exactly
    out[OUT_TRI + gid] = 0.f;                        // zero triplane
    if (gid < NCNT) g_cnt[gid] = 0.f;
    if (gid < 2*GCELLS) { g_ccnt[gid] = 0; g_cfill[gid] = 0; }
    if (gid < 5*16384) {                             // wcv transpose
        int blk = gid / 16384, r = gid % 16384;
        int o = r >> 9, c = (r >> 4) & 31, s = r & 15;
        g_wt[blk*16384 + (c*16+s)*32 + o] = wcv[gid];
    }
    if (gid < NPTOT*3) out[gid] = xyz[gid];          // output 0
    if (gid < NPTOT*64) {                            // stem
        int p = gid >> 6, d = gid & 63;
        float x = xyz[p*3+0], y = xyz[p*3+1], z = xyz[p*3+2];
        g_c[gid] = fmaf(z, ws[128+d], fmaf(y, ws[64+d], fmaf(x, ws[d], bs[d])));
        if (d == 0) {
            g_pts[p] = make_float4(x, y, z, fmaf(z, z, fmaf(y, y, x*x)));
            const float den = 1.101f;
            float px = x/den + 0.5f, py = y/den + 0.5f, pz = z/den + 0.5f;
            int ix = (int)(px*64.0f); ix = min(max(ix,0),63);
            int iy = (int)(py*64.0f); iy = min(max(iy,0),63);
            int iz = (int)(pz*64.0f); iz = min(max(iz,0),63);
            g_ij[p] = ix | (iy<<6) | (iz<<12);
        }
    }
}

// cell counting must run after g_ccnt is zeroed (separate launch)
__global__ void k_cellcnt() {
    int p = blockIdx.x*blockDim.x + threadIdx.x;
    if (p >= NPTOT) return;
    float4 q = g_pts[p];
    int cell = (p>>13)*GCELLS +
               (cellcoord(q.z)*16 + cellcoord(q.y))*16 + cellcoord(q.x);
    atomicAdd(&g_ccnt[cell], 1);
}

// ---------------- grid build ----------------
__global__ void k_scan() {
    __shared__ int part[256], off[256];
    int t = threadIdx.x;
    int base = t*32;
    int loc[32];
    int run = 0;
    #pragma unroll
    for (int j = 0; j < 32; j++) { loc[j] = run; run += g_ccnt[base+j]; }
    part[t] = run;
    __syncthreads();
    if (t < 32) {
        int tmp[8]; int s = 0;
        #pragma unroll
        for (int j = 0; j < 8; j++) { tmp[j] = s; s += part[t*8+j]; }
        int run2 = s;
        #pragma unroll
        for (int o2 = 1; o2 < 32; o2 <<= 1) {
            int v = __shfl_up_sync(0xffffffffu, run2, o2);
            if (t >= o2) run2 += v;
        }
        int excl = run2 - s;
        #pragma unroll
        for (int j = 0; j < 8; j++) off[t*8+j] = excl + tmp[j];
        if (t == 31) g_cstart[2*GCELLS] = excl + s;
    }
    __syncthreads();
    int o = off[t];
    #pragma unroll
    for (int j = 0; j < 32; j++) g_cstart[base+j] = loc[j] + o;
}

__global__ void k_gscat() {
    int p = blockIdx.x*blockDim.x + threadIdx.x;
    if (p >= NPTOT) return;
    float4 q = g_pts[p];
    int cell = (p>>13)*GCELLS +
               (cellcoord(q.z)*16 + cellcoord(q.y))*16 + cellcoord(q.x);
    int pos = g_cstart[cell] + atomicAdd(&g_cfill[cell], 1);
    g_sorted[pos] = q;
    g_sidx[pos] = p;
}

// ---------------- grid KNN: warp per query, exact with box-face guard ----------------
__global__ void __launch_bounds__(128) k_knng() {
    __shared__ float bufd[4][KCAP];
    __shared__ int   bufi[4][KCAP];
    __shared__ int   bcnt[4];

    int w = threadIdx.x >> 5, lane = threadIdx.x & 31;
    int p = blockIdx.x*4 + w;
    float4 Q = g_pts[p];
    int cbase = (p>>13)*GCELLS;
    int sbase = (p>>13)*NPTS;
    int cx = cellcoord(Q.x), cy = cellcoord(Q.y), cz = cellcoord(Q.z);
    const float h = 0.0625f;

    int r = 2;
    bool fb = false;
    for (;;) {
        int xlo = max(cx-r,0), xhi = min(cx+r,15);
        int ylo = max(cy-r,0), yhi = min(cy+r,15);
        int zlo = max(cz-r,0), zhi = min(cz+r,15);

        float lmin = 1e30f;
        int ord = 0;
        for (int z = zlo; z <= zhi; z++)
            for (int y = ylo; y <= yhi; y++) {
                int row = cbase + (z*16 + y)*16;
                int s0 = g_cstart[row + xlo];
                int s1 = g_cstart[row + xhi + 1];
                int len = s1 - s0;
                int t0 = (lane - ord) & 31;
                for (int t = t0; t < len; t += 32)
                    lmin = fminf(lmin, d2f(Q.x,Q.y,Q.z,Q.w, g_sorted[s0 + t]));
                ord += len;
            }
        if (ord < KNBR) { r++; continue; }

        float T = 0.f;
        {
            float vv = lmin;
            for (int rr = 0; rr < 16; rr++) {
                float mv = vv; int ml = lane;
                #pragma unroll
                for (int off = 16; off; off >>= 1) {
                    float ov = __shfl_xor_sync(0xffffffffu, mv, off);
                    int   ol = __shfl_xor_sync(0xffffffffu, ml, off);
                    if (ov < mv || (ov == mv && ol < ml)) { mv = ov; ml = ol; }
                }
                T = mv;
                if (lane == ml) vv = 1e30f;
            }
        }
        if (lane == 0) bcnt[w] = 0;
        __syncwarp();

        for (int z = zlo; z <= zhi; z++)
            for (int y = ylo; y <= yhi; y++) {
                int row = cbase + (z*16 + y)*16;
                int s0 = g_cstart[row + xlo];
                int s1 = g_cstart[row + xhi + 1];
                for (int j = s0 + lane; j < s1; j += 32) {
                    float dd = d2f(Q.x,Q.y,Q.z,Q.w, g_sorted[j]);
                    if (dd <= T) {
                        int pos = atomicAdd(&bcnt[w], 1);
                        if (pos < KCAP) { bufd[w][pos] = dd; bufi[w][pos] = g_sidx[j]; }
                    }
                }
            }
        __syncwarp();
        int cnt = bcnt[w];
        if (cnt > KCAP) { fb = true; break; }

        float d16 = 0.f;
        for (int rr = 0; rr < KNBR; rr++) {
            float lbd = 1e30f; int lbi = 0x7fffffff; int lpos = -1;
            for (int j = lane; j < cnt; j += 32) {
                float d = bufd[w][j]; int ii = bufi[w][j];
                if (d < lbd || (d == lbd && ii < lbi)) { lbd = d; lbi = ii; lpos = j; }
            }
            float bd = lbd; int bi = lbi;
            #pragma unroll
            for (int off = 16; off; off >>= 1) {
                float od = __shfl_xor_sync(0xffffffffu, bd, off);
                int   oi = __shfl_xor_sync(0xffffffffu, bi, off);
                if (od < bd || (od == bd && oi < bi)) { bd = od; bi = oi; }
            }
            if (lpos >= 0 && lbi == bi) bufd[w][lpos] = 1e30f;
            if (lane == 0) g_idx[p*KNBR + rr] = bi;
            d16 = bd;
            __syncwarp();
        }

        float g = 1e30f;
        if (xlo > 0)  g = fminf(g, Q.x - (-0.5f + xlo*h));
        if (xhi < 15) g = fminf(g, (-0.5f + (xhi+1)*h) - Q.x);
        if (ylo > 0)  g = fminf(g, Q.y - (-0.5f + ylo*h));
        if (yhi < 15) g = fminf(g, (-0.5f + (yhi+1)*h) - Q.y);
        if (zlo > 0)  g = fminf(g, Q.z - (-0.5f + zlo*h));
        if (zhi < 15) g = fminf(g, (-0.5f + (zhi+1)*h) - Q.z);
        if (d16 < g*g*0.99999f) break;
        r++;
        if (r > 18) break;
    }

    if (fb && lane == 0) {
        const float4* pts = g_pts + sbase;
        float td[KNBR]; int ti[KNBR];
        #pragma unroll
        for (int rr = 0; rr < KNBR; rr++) { td[rr] = 1e30f; ti[rr] = 0x7fffffff; }
        for (int m = 0; m < NPTS; m++) {
            float dd = d2f(Q.x,Q.y,Q.z,Q.w, pts[m]);
            if (dd < td[KNBR-1] || (dd == td[KNBR-1] && m < ti[KNBR-1])) {
                float cd = dd; int ci = m;
                #pragma unroll
                for (int rr = 0; rr < KNBR; rr++) {
                    bool lt = (cd < td[rr]) || (cd == td[rr] && ci < ti[rr]);
                    if (lt) { float t1=td[rr]; int t2=ti[rr]; td[rr]=cd; ti[rr]=ci; cd=t1; ci=t2; }
                }
            }
        }
        for (int rr = 0; rr < KNBR; rr++) g_idx[p*KNBR + rr] = sbase + ti[rr];
    }
}

// ---------------- x = relu(c @ w0 + b0) -> buffer A ----------------
__global__ void k_xup(const float* __restrict__ w0, const float* __restrict__ b0) {
    int gid = blockIdx.x*blockDim.x + threadIdx.x;
    if (gid >= NPTOT*32) return;
    int n = gid >> 5, h = gid & 31;
    const float* cr = g_c + n*64;
    float a0 = b0[h], a1 = 0.f;
    #pragma unroll
    for (int d = 0; d < 64; d += 2) {
        a0 = fmaf(cr[d],   w0[d*32+h],     a0);
        a1 = fmaf(cr[d+1], w0[(d+1)*32+h], a1);
    }
    g_xA[gid] = fmaxf(a0 + a1, 0.f);
}

// ---------------- fused FKAConv + w2 + residual + next-block x; CTA = 8 points ----------------
// last block: also writes outc and does the triplane scatter inline (no k_scatter pass).
__global__ void __launch_bounds__(128) k_fka(int blk, int last, int bufsel,
    const float* __restrict__ fc1, const float* __restrict__ fc2,
    const float* __restrict__ fc3, const float* __restrict__ alpha,
    const float* __restrict__ beta, const float* __restrict__ w2,
    const float* __restrict__ b2, const float* __restrict__ w0n,
    const float* __restrict__ b0n, float* __restrict__ outc,
    float* __restrict__ tri)
{
    __shared__ float sfc1[48], sfc2[512], sfc3[512];
    __shared__ float sM[2048];   // [warp][pt][k][s]; reused as sC[warp][pt][64]
    __shared__ float sF[4096];   // [ptCTA 0..7][cs 0..511]
    __shared__ float sP[1024];   // [warp][ptCTA][o] wcv partials
    __shared__ float sR[256];    // [ptCTA][o]
    __shared__ int   sI[128];    // [ptCTA][k]

    const float* __restrict__ xin  = bufsel ? g_xB : g_xA;
    float* __restrict__       xout = bufsel ? g_xA : g_xB;

    int tid = threadIdx.x, w = tid >> 5, lane = tid & 31;
    for (int i = tid; i < 48;  i += 128) sfc1[i] = fc1[i];
    for (int i = tid; i < 512; i += 128) { sfc2[i] = fc2[i]; sfc3[i] = fc3[i]; }
    __syncthreads();

    int half = lane >> 4, k = lane & 15;
    int hbase = lane & 16;
    int p = blockIdx.x*8 + w*2 + half;
    int ik = g_idx[p*KNBR + k];
    sI[(w*2+half)*16 + k] = ik;
    float4 q  = g_pts[p];
    float4 nb = g_pts[ik];
    float dx = nb.x-q.x, dy = nb.y-q.y, dz = nb.z-q.z;
    float dist = sqrtf(dx*dx + dy*dy + dz*dz + 1e-12f);
    float zz = beta[0] - alpha[0]*dist;
    float dwr = 1.0f/(1.0f + expf(-zz));
    float sm = dwr;
    #pragma unroll
    for (int off = 8; off; off >>= 1) sm += __shfl_xor_sync(0xffffffffu, sm, off);
    float dw = dwr / (sm + 1e-6f) * 16.0f;

    float a[16], b[16], c2[16];
    #pragma unroll
    for (int s = 0; s < 16; s++)
        a[s] = fmaxf(fmaf(dx, sfc1[s], fmaf(dy, sfc1[16+s], dz*sfc1[32+s])), 0.f);
    #pragma unroll
    for (int s = 0; s < 16; s++) {
        float v = a[s]*dw;
        #pragma unroll
        for (int off = 8; off; off >>= 1) v = fmaxf(v, __shfl_xor_sync(0xffffffffu, v, off));
        b[s] = v;
    }
    // fc2: a-part per lane; b-part identical across the half -> own-column + shuffle
    {
        float bp = 0.f;
        #pragma unroll
        for (int r = 0; r < 16; r++) bp = fmaf(b[r], sfc2[(16+r)*16 + k], bp);
        #pragma unroll
        for (int s = 0; s < 16; s++) c2[s] = 0.f;
        #pragma unroll 4
        for (int r = 0; r < 16; r++) {
            float va = a[r];
            #pragma unroll
            for (int s = 0; s < 16; s++)
                c2[s] = fmaf(va, sfc2[r*16+s], c2[s]);
        }
        #pragma unroll
        for (int s = 0; s < 16; s++)
            c2[s] += __shfl_sync(0xffffffffu, bp, hbase + s);
    }
    #pragma unroll
    for (int s = 0; s < 16; s++) a[s] = fmaxf(c2[s], 0.f);
    #pragma unroll
    for (int s = 0; s < 16; s++) {
        float v = a[s]*dw;
        #pragma unroll
        for (int off = 8; off; off >>= 1) v = fmaxf(v, __shfl_xor_sync(0xffffffffu, v, off));
        b[s] = v;
    }
    // fc3: same dedup
    {
        float bp = 0.f;
        #pragma unroll
        for (int r = 0; r < 16; r++) bp = fmaf(b[r], sfc3[(16+r)*16 + k], bp);
        #pragma unroll
        for (int s = 0; s < 16; s++) c2[s] = 0.f;
        #pragma unroll 4
        for (int r = 0; r < 16; r++) {
            float va = a[r];
            #pragma unroll
            for (int s = 0; s < 16; s++)
                c2[s] = fmaf(va, sfc3[r*16+s], c2[s]);
        }
        #pragma unroll
        for (int s = 0; s < 16; s++)
            c2[s] += __shfl_sync(0xffffffffu, bp, hbase + s);
    }
    {   // m = relu(m3)*dw -> smem
        float4* md = (float4*)&sM[((w*2+half)*16 + k)*16];
        md[0] = make_float4(fmaxf(c2[0],0.f)*dw, fmaxf(c2[1],0.f)*dw,
                            fmaxf(c2[2],0.f)*dw, fmaxf(c2[3],0.f)*dw);
        md[1] = make_float4(fmaxf(c2[4],0.f)*dw, fmaxf(c2[5],0.f)*dw,
                            fmaxf(c2[6],0.f)*dw, fmaxf(c2[7],0.f)*dw);
        md[2] = make_float4(fmaxf(c2[8],0.f)*dw, fmaxf(c2[9],0.f)*dw,
                            fmaxf(c2[10],0.f)*dw, fmaxf(c2[11],0.f)*dw);
        md[3] = make_float4(fmaxf(c2[12],0.f)*dw, fmaxf(c2[13],0.f)*dw,
                            fmaxf(c2[14],0.f)*dw, fmaxf(c2[15],0.f)*dw);
    }
    __syncwarp();

    // f[c][s] = sum_k nb_x[k][c]*m[k][s]; lane = c (own warp's 2 points)
    #pragma unroll
    for (int pt = 0; pt < 2; pt++) {
        float f[16];
        #pragma unroll
        for (int s = 0; s < 16; s++) f[s] = 0.f;
        const int* ip = &sI[(w*2+pt)*16];
        #pragma unroll 4
        for (int kk = 0; kk < 16; kk++) {
            float nbx = xin[ip[kk]*32 + lane];
            const float4* mv = (const float4*)&sM[((w*2+pt)*16 + kk)*16];
            float4 v0 = mv[0], v1 = mv[1], v2 = mv[2], v3 = mv[3];
            f[0]=fmaf(nbx,v0.x,f[0]);  f[1]=fmaf(nbx,v0.y,f[1]);
            f[2]=fmaf(nbx,v0.z,f[2]);  f[3]=fmaf(nbx,v0.w,f[3]);
            f[4]=fmaf(nbx,v1.x,f[4]);  f[5]=fmaf(nbx,v1.y,f[5]);
            f[6]=fmaf(nbx,v1.z,f[6]);  f[7]=fmaf(nbx,v1.w,f[7]);
            f[8]=fmaf(nbx,v2.x,f[8]);  f[9]=fmaf(nbx,v2.y,f[9]);
            f[10]=fmaf(nbx,v2.z,f[10]); f[11]=fmaf(nbx,v2.w,f[11]);
            f[12]=fmaf(nbx,v3.x,f[12]); f[13]=fmaf(nbx,v3.y,f[13]);
            f[14]=fmaf(nbx,v3.z,f[14]); f[15]=fmaf(nbx,v3.w,f[15]);
        }
        float4* fd = (float4*)&sF[(w*2+pt)*512 + lane*16];
        fd[0] = make_float4(f[0],f[1],f[2],f[3]);
        fd[1] = make_float4(f[4],f[5],f[6],f[7]);
        fd[2] = make_float4(f[8],f[9],f[10],f[11]);
        fd[3] = make_float4(f[12],f[13],f[14],f[15]);
    }
    __syncthreads();

    // wcv: warp w covers cs in [w*128,(w+1)*128), accumulates ALL 8 CTA points.
    {
        int csoff = lane >> 3, o0 = (lane & 7) << 2;
        const float* wtb = g_wt + blk*16384;
        float acc[8][4];
        #pragma unroll
        for (int pt = 0; pt < 8; pt++)
            #pragma unroll
            for (int j = 0; j < 4; j++) acc[pt][j] = 0.f;
        int wbase = w*128;
        #pragma unroll 4
        for (int g2 = 0; g2 < 32; g2++) {
            int cs = wbase + (g2<<2) + csoff;
            float4 wv = *(const float4*)(wtb + (cs<<5) + o0);
            #pragma unroll
            for (int pt = 0; pt < 8; pt++) {
                float fv = sF[pt*512 + cs];
                acc[pt][0]=fmaf(fv,wv.x,acc[pt][0]);
                acc[pt][1]=fmaf(fv,wv.y,acc[pt][1]);
                acc[pt][2]=fmaf(fv,wv.z,acc[pt][2]);
                acc[pt][3]=fmaf(fv,wv.w,acc[pt][3]);
            }
        }
        #pragma unroll
        for (int off = 8; off <= 16; off <<= 1) {
            #pragma unroll
            for (int pt = 0; pt < 8; pt++) {
                acc[pt][0] += __shfl_xor_sync(0xffffffffu, acc[pt][0], off);
                acc[pt][1] += __shfl_xor_sync(0xffffffffu, acc[pt][1], off);
                acc[pt][2] += __shfl_xor_sync(0xffffffffu, acc[pt][2], off);
                acc[pt][3] += __shfl_xor_sync(0xffffffffu, acc[pt][3], off);
            }
        }
        if (csoff == 0) {
            #pragma unroll
            for (int pt = 0; pt < 8; pt++)
                *(float4*)&sP[(w*8 + pt)*32 + o0] =
                    make_float4(acc[pt][0], acc[pt][1], acc[pt][2], acc[pt][3]);
        }
    }
    __syncthreads();

    // cross-warp reduce + relu -> sR[pt*32+o]
    {
        #pragma unroll
        for (int ii = 0; ii < 2; ii++) {
            int idx = tid*2 + ii;
            float s = sP[idx] + sP[256+idx] + sP[512+idx] + sP[768+idx];
            sR[idx] = fmaxf(s, 0.f);
        }
    }
    __syncwarp();

    // c = relu(r @ w2 + b2 + c); coalesced scalar w2 loads
    float* sC = &sM[w*512];
    int d0 = lane, d1 = lane + 32;
    #pragma unroll
    for (int pt = 0; pt < 2; pt++) {
        int p2 = blockIdx.x*8 + w*2 + pt;
        float acc0 = b2[d0], acc1 = b2[d1];
        const float* rr = &sR[(w*2+pt)*32];
        #pragma unroll 8
        for (int h = 0; h < 32; h++) {
            float rh = rr[h];
            acc0 = fmaf(rh, w2[h*64 + d0], acc0);
            acc1 = fmaf(rh, w2[h*64 + d1], acc1);
        }
        float c0 = g_c[p2*64 + d0], c1 = g_c[p2*64 + d1];
        float v0 = fmaxf(acc0 + c0, 0.f), v1 = fmaxf(acc1 + c1, 0.f);
        if (!last) {
            g_c[p2*64 + d0] = v0;
            g_c[p2*64 + d1] = v1;
            sC[pt*64 + d0] = v0;
            sC[pt*64 + d1] = v1;
        } else {
            // final block: write output c and scatter to triplane inline
            outc[p2*64 + d0] = v0;
            outc[p2*64 + d1] = v1;
            int code = g_ij[p2];
            int i0 = code & 63, i1 = (code>>6)&63, i2 = (code>>12)&63;
            int base = (p2 >> 13) * 3 * 4096;
            int c01 = base + (i0*64+i1);
            int c02 = base + 4096 + (i0*64+i2);
            int c12 = base + 8192 + (i1*64+i2);
            atomicAdd(&tri[c01*64 + d0], v0);
            atomicAdd(&tri[c02*64 + d0], v0);
            atomicAdd(&tri[c12*64 + d0], v0);
            atomicAdd(&tri[c01*64 + d1], v1);
            atomicAdd(&tri[c02*64 + d1], v1);
            atomicAdd(&tri[c12*64 + d1], v1);
            if (lane == 0) {
                atomicAdd(&g_cnt[c01], 1.f);
                atomicAdd(&g_cnt[c02], 1.f);
                atomicAdd(&g_cnt[c12], 1.f);
            }
        }
    }
    __syncwarp();

    // next block's x = relu(c_new @ w0n + b0n) into the OTHER buffer (no race)
    if (!last) {
        #pragma unroll
        for (int pt = 0; pt < 2; pt++) {
            int p2 = blockIdx.x*8 + w*2 + pt;
            const float* cc = &sC[pt*64];
            float acc = b0n[lane];
            #pragma unroll 16
            for (int d = 0; d < 64; d++)
                acc = fmaf(cc[d], w0n[d*32 + lane], acc);
            xout[p2*32 + lane] = fmaxf(acc, 0.f);
        }
    }
}

// ---------------- triplane normalize ----------------
__global__ void k_norm(float* __restrict__ tri) {
    int gid = blockIdx.x*blockDim.x + threadIdx.x;
    if (gid >= NTRI) return;
    tri[gid] = tri[gid] / fmaxf(g_cnt[gid >> 6], 1.f);
}

extern "C" void kernel_launch(void* const* d_in, const int* in_sizes, int n_in,
                              void* d_out, int out_size) {
    const float* xyz    = (const float*)d_in[0];
    const float* w_stem = (const float*)d_in[1];
    const float* b_stem = (const float*)d_in[2];
    const float* w0     = (const float*)d_in[3];
    const float* b0     = (const float*)d_in[4];
    const float* fc1    = (const float*)d_in[5];
    const float* fc2    = (const float*)d_in[6];
    const float* fc3    = (const float*)d_in[7];
    const float* wcv    = (const float*)d_in[8];
    const float* alpha  = (const float*)d_in[9];
    const float* beta   = (const float*)d_in[10];
    const float* w2     = (const float*)d_in[11];
    const float* b2     = (const float*)d_in[12];
    float* out = (float*)d_out;

    k_prep<<<6144, 256>>>(xyz, w_stem, b_stem, wcv, out);
    k_cellcnt<<<64, 256>>>();
    k_scan<<<1, 256>>>();
    k_gscat<<<64, 256>>>();
    k_knng<<<4096, 128>>>();
    k_xup<<<2048, 256>>>(w0, b0);
    for (int i = 0; i < 5; i++) {
        int last = (i == 4);
        k_fka<<<2048, 128>>>(i, last, i & 1,
                             fc1 + i*48, fc2 + i*512, fc3 + i*512,
                             alpha + i, beta + i, w2 + i*2048, b2 + i*64,
                             w0 + (last ? 0 : (i+1)*2048),
                             b0 + (last ? 0 : (i+1)*32),
                             out + OUT_C, out + OUT_TRI);
    }
    k_norm<<<6144, 256>>>(out + OUT_TRI);
}